// round 1
// baseline (speedup 1.0000x reference)
#include <cuda_runtime.h>

// CorrTorch: 3D correlation, max_displacement=1.
// in1, in2: [1, 64, 64, 128, 128] fp32  (C=64, D=64, H=128, W=128)
// out:      [1, 27, 64, 128, 128] fp32, k = dz*9 + dy*3 + dx, source plane d+dz-1 etc.
//
// Strategy: each thread owns a 4-wide w strip at one (d,h); 27x4 = 108 fp32
// accumulators in registers. Per channel: 1 LDG.128 (in1) + 9 rows x
// (pred LDG.32 + LDG.128 + pred LDG.32) for in2, row registers reused across
// the 3 dx taps. Boundary zero-pad via uniform per-thread predicates.

namespace {
constexpr int C  = 64;
constexpr int DD = 64;
constexpr int HH = 128;
constexpr int WW = 128;
constexpr int HW = HH * WW;        // 16384
constexpr int CS = DD * HW;        // 1048576 (channel stride; also per-k output stride)
constexpr int STRIPS = DD * HH * (WW / 4);   // 262144
constexpr int TPB = 128;
}

__global__ void __launch_bounds__(TPB) corr3d_kernel(
    const float* __restrict__ in1,
    const float* __restrict__ in2,
    float* __restrict__ out)
{
    int s = blockIdx.x * TPB + threadIdx.x;   // strip id
    int w0 = (s & 31) << 2;                    // 0,4,...,124
    int h  = (s >> 5) & 127;
    int d  = s >> 12;

    const float* p1 = in1 + d * HW + h * WW + w0;
    // corner pointer (may be "out of bounds" arithmetically; guarded loads only)
    const float* p2 = in2 + (d - 1) * HW + (h - 1) * WW + (w0 - 1);

    const bool pdz[3] = { d > 0,  true, d < DD - 1 };
    const bool pdy[3] = { h > 0,  true, h < HH - 1 };
    const bool pw0 = (w0 > 0);
    const bool pw5 = (w0 < WW - 4);

    float acc[27][4];
#pragma unroll
    for (int k = 0; k < 27; k++) {
        acc[k][0] = 0.f; acc[k][1] = 0.f; acc[k][2] = 0.f; acc[k][3] = 0.f;
    }

    const float* q1 = p1;
    const float* q2 = p2;
    for (int c = 0; c < C; c++) {
        float4 a = *reinterpret_cast<const float4*>(q1);
#pragma unroll
        for (int dz = 0; dz < 3; dz++) {
#pragma unroll
            for (int dy = 0; dy < 3; dy++) {
                const bool rv = pdz[dz] && pdy[dy];
                const float* rp = q2 + dz * HW + dy * WW;
                float r0 = (rv && pw0) ? rp[0] : 0.f;
                float4 rm = rv ? *reinterpret_cast<const float4*>(rp + 1)
                               : make_float4(0.f, 0.f, 0.f, 0.f);
                float r5 = (rv && pw5) ? rp[5] : 0.f;
                float r[6] = { r0, rm.x, rm.y, rm.z, rm.w, r5 };
#pragma unroll
                for (int dx = 0; dx < 3; dx++) {
                    const int k = dz * 9 + dy * 3 + dx;
                    acc[k][0] += a.x * r[dx + 0];
                    acc[k][1] += a.y * r[dx + 1];
                    acc[k][2] += a.z * r[dx + 2];
                    acc[k][3] += a.w * r[dx + 3];
                }
            }
        }
        q1 += CS;
        q2 += CS;
    }

    float* op = out + d * HW + h * WW + w0;
    const float inv = 1.0f / 64.0f;
#pragma unroll
    for (int k = 0; k < 27; k++) {
        float4 v = make_float4(acc[k][0] * inv, acc[k][1] * inv,
                               acc[k][2] * inv, acc[k][3] * inv);
        *reinterpret_cast<float4*>(op + (long)k * CS) = v;
    }
}

extern "C" void kernel_launch(void* const* d_in, const int* in_sizes, int n_in,
                              void* d_out, int out_size)
{
    const float* in1 = (const float*)d_in[0];
    const float* in2 = (const float*)d_in[1];
    float* out = (float*)d_out;
    (void)in_sizes; (void)n_in; (void)out_size;

    corr3d_kernel<<<STRIPS / TPB, TPB>>>(in1, in2, out);
}

// round 2
// speedup vs baseline: 2.5794x; 2.5794x over previous
#include <cuda_runtime.h>

// CorrTorch 3D correlation, max_displacement=1.
// in1, in2: [1, 64, 64, 128, 128] fp32; out: [1, 27, 64, 128, 128] fp32.
//
// R1 -> R2 change: split the 27 displacement taps by dz across threadIdx.y
// (3 groups per block). Each thread keeps only 9 accumulators x 4-wide strip
// (36 fp32) instead of 108, cutting regs/thread ~128 -> ~64 and lifting
// occupancy ~2-3x. All 3 dz groups sit in one block so the in1 LDG.128 is
// L1-deduped and adjacent-d blocks share in2 planes in L2.

namespace {
constexpr int C  = 64;
constexpr int DD = 64;
constexpr int HH = 128;
constexpr int WW = 128;
constexpr int HW = HH * WW;        // 16384
constexpr int CS = DD * HW;        // 1048576 (channel stride == per-k out stride)
constexpr int TPX = 128;           // strips per block
constexpr int NBLK = DD * HH * (WW / 4) / TPX;   // 2048
}

__global__ void __launch_bounds__(TPX * 3) corr3d_kernel(
    const float* __restrict__ in1,
    const float* __restrict__ in2,
    float* __restrict__ out)
{
    const int s  = blockIdx.x * TPX + threadIdx.x;  // strip id
    const int dz = threadIdx.y;                     // 0..2
    const int w0 = (s & 31) << 2;                   // 0,4,...,124
    const int h  = (s >> 5) & 127;
    const int d  = s >> 12;

    const int zp = d + dz - 1;                      // in2 source plane
    const bool pz = (zp >= 0) && (zp < DD);
    const bool pdy[3] = { h > 0, true, h < HH - 1 };
    const bool pw0 = (w0 > 0);
    const bool pw5 = (w0 < WW - 4);

    const float* q1 = in1 + d * HW + h * WW + w0;
    // corner pointer for this dz plane (guarded loads only)
    const float* q2 = in2 + zp * HW + (h - 1) * WW + (w0 - 1);

    float acc[9][4];
#pragma unroll
    for (int k = 0; k < 9; k++) {
        acc[k][0] = 0.f; acc[k][1] = 0.f; acc[k][2] = 0.f; acc[k][3] = 0.f;
    }

#pragma unroll 2
    for (int c = 0; c < C; c++) {
        float4 a = *reinterpret_cast<const float4*>(q1);
        float r[3][6];
#pragma unroll
        for (int dy = 0; dy < 3; dy++) {
            const bool rv = pz && pdy[dy];
            const float* rp = q2 + dy * WW;
            float  r0 = (rv && pw0) ? rp[0] : 0.f;
            float4 rm = rv ? *reinterpret_cast<const float4*>(rp + 1)
                           : make_float4(0.f, 0.f, 0.f, 0.f);
            float  r5 = (rv && pw5) ? rp[5] : 0.f;
            r[dy][0] = r0; r[dy][1] = rm.x; r[dy][2] = rm.y;
            r[dy][3] = rm.z; r[dy][4] = rm.w; r[dy][5] = r5;
        }
#pragma unroll
        for (int dy = 0; dy < 3; dy++) {
#pragma unroll
            for (int dx = 0; dx < 3; dx++) {
                const int k = dy * 3 + dx;
                acc[k][0] += a.x * r[dy][dx + 0];
                acc[k][1] += a.y * r[dy][dx + 1];
                acc[k][2] += a.z * r[dy][dx + 2];
                acc[k][3] += a.w * r[dy][dx + 3];
            }
        }
        q1 += CS;
        q2 += CS;
    }

    float* op = out + (long)(dz * 9) * CS + d * HW + h * WW + w0;
    const float inv = 1.0f / 64.0f;
#pragma unroll
    for (int k = 0; k < 9; k++) {
        float4 v = make_float4(acc[k][0] * inv, acc[k][1] * inv,
                               acc[k][2] * inv, acc[k][3] * inv);
        *reinterpret_cast<float4*>(op + (long)k * CS) = v;
    }
}

extern "C" void kernel_launch(void* const* d_in, const int* in_sizes, int n_in,
                              void* d_out, int out_size)
{
    const float* in1 = (const float*)d_in[0];
    const float* in2 = (const float*)d_in[1];
    float* out = (float*)d_out;
    (void)in_sizes; (void)n_in; (void)out_size;

    dim3 blk(TPX, 3);
    corr3d_kernel<<<NBLK, blk>>>(in1, in2, out);
}

// round 3
// speedup vs baseline: 3.3709x; 1.3069x over previous
#include <cuda_runtime.h>

// CorrTorch 3D correlation, max_displacement=1.
// in1, in2: [1, 64, 64, 128, 128] fp32; out: [1, 27, 64, 128, 128] fp32.
//
// R2 -> R3: each warp covers one full W row (lane i owns w=4i..4i+3), so the
// dx = -1 / +1 halo values are the neighbor lanes' registers. Replace the 6
// edge LDG.32s per channel with 6 SHFLs: loads drop 10 -> 4 per channel
// (L1 wavefronts 40 -> 16 per warp-channel). Row-edge zeros fall out since
// lane 0 / lane 31 are exactly the w boundaries. Blocks shrunk to (64,3) with
// launch_bounds(192,5) for better reg-limited occupancy.

namespace {
constexpr int C  = 64;
constexpr int DD = 64;
constexpr int HH = 128;
constexpr int WW = 128;
constexpr int HW = HH * WW;        // 16384
constexpr int CS = DD * HW;        // 1048576 (channel stride == per-k out stride)
constexpr int TPX = 64;            // strips per block (2 warps in x)
constexpr int NBLK = DD * HH * (WW / 4) / TPX;   // 4096
}

__global__ void __launch_bounds__(TPX * 3, 5) corr3d_kernel(
    const float* __restrict__ in1,
    const float* __restrict__ in2,
    float* __restrict__ out)
{
    const int s  = blockIdx.x * TPX + threadIdx.x;  // strip id
    const int dz = threadIdx.y;                     // 0..2
    const int lane = threadIdx.x & 31;
    const int w0 = (s & 31) << 2;                   // 0,4,...,124
    const int h  = (s >> 5) & 127;
    const int d  = s >> 12;

    const int zp = d + dz - 1;                      // in2 source plane
    const bool pz = (zp >= 0) && (zp < DD);
    const bool rv[3] = { pz && (h > 0), pz, pz && (h < HH - 1) };
    const bool pw0 = (lane > 0);    // w0 > 0
    const bool pw5 = (lane < 31);   // w0 < 124

    const float* q1 = in1 + d * HW + h * WW + w0;
    const float* q2 = in2 + zp * HW + (h - 1) * WW + w0;  // aligned, row h-1

    float acc[9][4];
#pragma unroll
    for (int k = 0; k < 9; k++) {
        acc[k][0] = 0.f; acc[k][1] = 0.f; acc[k][2] = 0.f; acc[k][3] = 0.f;
    }

#pragma unroll 2
    for (int c = 0; c < C; c++) {
        float4 a = *reinterpret_cast<const float4*>(q1);
        float r[3][6];
#pragma unroll
        for (int dy = 0; dy < 3; dy++) {
            float4 rm = rv[dy] ? *reinterpret_cast<const float4*>(q2 + dy * WW)
                               : make_float4(0.f, 0.f, 0.f, 0.f);
            float lo = __shfl_up_sync(0xffffffffu, rm.w, 1);
            float hi = __shfl_down_sync(0xffffffffu, rm.x, 1);
            r[dy][0] = pw0 ? lo : 0.f;
            r[dy][1] = rm.x; r[dy][2] = rm.y; r[dy][3] = rm.z; r[dy][4] = rm.w;
            r[dy][5] = pw5 ? hi : 0.f;
        }
#pragma unroll
        for (int dy = 0; dy < 3; dy++) {
#pragma unroll
            for (int dx = 0; dx < 3; dx++) {
                const int k = dy * 3 + dx;
                acc[k][0] += a.x * r[dy][dx + 0];
                acc[k][1] += a.y * r[dy][dx + 1];
                acc[k][2] += a.z * r[dy][dx + 2];
                acc[k][3] += a.w * r[dy][dx + 3];
            }
        }
        q1 += CS;
        q2 += CS;
    }

    float* op = out + (long)(dz * 9) * CS + d * HW + h * WW + w0;
    const float inv = 1.0f / 64.0f;
#pragma unroll
    for (int k = 0; k < 9; k++) {
        float4 v = make_float4(acc[k][0] * inv, acc[k][1] * inv,
                               acc[k][2] * inv, acc[k][3] * inv);
        *reinterpret_cast<float4*>(op + (long)k * CS) = v;
    }
}

extern "C" void kernel_launch(void* const* d_in, const int* in_sizes, int n_in,
                              void* d_out, int out_size)
{
    const float* in1 = (const float*)d_in[0];
    const float* in2 = (const float*)d_in[1];
    float* out = (float*)d_out;
    (void)in_sizes; (void)n_in; (void)out_size;

    dim3 blk(TPX, 3);
    corr3d_kernel<<<NBLK, blk>>>(in1, in2, out);
}

// round 4
// speedup vs baseline: 4.6076x; 1.3669x over previous
#include <cuda_runtime.h>

// CorrTorch 3D correlation, max_displacement=1.
// in1, in2: [1, 64, 64, 128, 128] fp32; out: [1, 27, 64, 128, 128] fp32.
//
// R3 -> R4: explicit 2-stage register double-buffering of the channel loop.
// Loads for channel c+1 are issued before the compute of channel c, so the
// ~250cyc L2 latency overlaps the 36 FMA + 6 SHFL compute block. launch_bounds
// relaxed (192,5)->(192,4) to give ptxas the register headroom the pipeline
// needs (R3's 68-reg cap blocked load hoisting).

namespace {
constexpr int C  = 64;
constexpr int DD = 64;
constexpr int HH = 128;
constexpr int WW = 128;
constexpr int HW = HH * WW;        // 16384
constexpr int CS = DD * HW;        // 1048576 (channel stride == per-k out stride)
constexpr int TPX = 64;            // strips per block (2 warps in x)
constexpr int NBLK = DD * HH * (WW / 4) / TPX;   // 4096
}

__device__ __forceinline__ void ld_stage(const float* __restrict__ q1,
                                         const float* __restrict__ q2,
                                         const bool rv[3],
                                         float4& a, float4 rm[3])
{
    a = *reinterpret_cast<const float4*>(q1);
#pragma unroll
    for (int dy = 0; dy < 3; dy++) {
        rm[dy] = rv[dy] ? *reinterpret_cast<const float4*>(q2 + dy * WW)
                        : make_float4(0.f, 0.f, 0.f, 0.f);
    }
}

__device__ __forceinline__ void do_compute(const float4& a, const float4 rm[3],
                                           float acc[9][4], bool pw0, bool pw5)
{
#pragma unroll
    for (int dy = 0; dy < 3; dy++) {
        float lo = __shfl_up_sync(0xffffffffu, rm[dy].w, 1);
        float hi = __shfl_down_sync(0xffffffffu, rm[dy].x, 1);
        float r[6];
        r[0] = pw0 ? lo : 0.f;
        r[1] = rm[dy].x; r[2] = rm[dy].y; r[3] = rm[dy].z; r[4] = rm[dy].w;
        r[5] = pw5 ? hi : 0.f;
#pragma unroll
        for (int dx = 0; dx < 3; dx++) {
            const int k = dy * 3 + dx;
            acc[k][0] += a.x * r[dx + 0];
            acc[k][1] += a.y * r[dx + 1];
            acc[k][2] += a.z * r[dx + 2];
            acc[k][3] += a.w * r[dx + 3];
        }
    }
}

__global__ void __launch_bounds__(TPX * 3, 4) corr3d_kernel(
    const float* __restrict__ in1,
    const float* __restrict__ in2,
    float* __restrict__ out)
{
    const int s  = blockIdx.x * TPX + threadIdx.x;  // strip id
    const int dz = threadIdx.y;                     // 0..2
    const int lane = threadIdx.x & 31;
    const int w0 = (s & 31) << 2;                   // 0,4,...,124
    const int h  = (s >> 5) & 127;
    const int d  = s >> 12;

    const int zp = d + dz - 1;                      // in2 source plane
    const bool pz = (zp >= 0) && (zp < DD);
    const bool rv[3] = { pz && (h > 0), pz, pz && (h < HH - 1) };
    const bool pw0 = (lane > 0);    // w0 > 0
    const bool pw5 = (lane < 31);   // w0 < 124

    const float* q1 = in1 + d * HW + h * WW + w0;
    const float* q2 = in2 + zp * HW + (h - 1) * WW + w0;  // aligned, row h-1

    float acc[9][4];
#pragma unroll
    for (int k = 0; k < 9; k++) {
        acc[k][0] = 0.f; acc[k][1] = 0.f; acc[k][2] = 0.f; acc[k][3] = 0.f;
    }

    float4 aA, aB;
    float4 rmA[3], rmB[3];

    ld_stage(q1, q2, rv, aA, rmA);                  // c = 0

#pragma unroll 2
    for (int c = 0; c < C - 2; c += 2) {
        q1 += CS; q2 += CS;
        ld_stage(q1, q2, rv, aB, rmB);              // c+1 in flight
        do_compute(aA, rmA, acc, pw0, pw5);         // consume c
        q1 += CS; q2 += CS;
        ld_stage(q1, q2, rv, aA, rmA);              // c+2 in flight
        do_compute(aB, rmB, acc, pw0, pw5);         // consume c+1
    }
    q1 += CS; q2 += CS;
    ld_stage(q1, q2, rv, aB, rmB);                  // c = C-1
    do_compute(aA, rmA, acc, pw0, pw5);
    do_compute(aB, rmB, acc, pw0, pw5);

    float* op = out + (long)(dz * 9) * CS + d * HW + h * WW + w0;
    const float inv = 1.0f / 64.0f;
#pragma unroll
    for (int k = 0; k < 9; k++) {
        float4 v = make_float4(acc[k][0] * inv, acc[k][1] * inv,
                               acc[k][2] * inv, acc[k][3] * inv);
        *reinterpret_cast<float4*>(op + (long)k * CS) = v;
    }
}

extern "C" void kernel_launch(void* const* d_in, const int* in_sizes, int n_in,
                              void* d_out, int out_size)
{
    const float* in1 = (const float*)d_in[0];
    const float* in2 = (const float*)d_in[1];
    float* out = (float*)d_out;
    (void)in_sizes; (void)n_in; (void)out_size;

    dim3 blk(TPX, 3);
    corr3d_kernel<<<NBLK, blk>>>(in1, in2, out);
}